// round 16
// baseline (speedup 1.0000x reference)
#include <cuda_runtime.h>
#include <cuda_bf16.h>
#include <cstdint>

// YOLOv5 detect head, two-kernel scheme:
//  K1: stream-convert p0/p1/p2/w* fp32 -> bf16 into __device__ scratch.
//  K2: unified bf16 GEMM (mma.m16n8k16). CTA 128m x 128n, K chunks of 64,
//      3-stage cp.async ring from bf16 gmem, ldmatrix fragments
//      (A: x4.trans from [k][m] 272B rows; B: x4 from [n][k] 144B rows;
//      both conflict-free), scattered decode epilogue.

#define A_ROW_B 272                    // 128 bf16 (256B) + 16B pad (17 units: 17r%8==r)
#define A_ST_BYTES (64 * A_ROW_B)      // 17408
#define B_ROW_B 144                    // 64 bf16 (128B) + 16B pad (9 units: 9r%8==r)
#define B_ST_BYTES (128 * B_ROW_B)     // 18432
#define STAGE_B (A_ST_BYTES + B_ST_BYTES)  // 35840
#define NST 3
#define DSMEM (NST * STAGE_B)          // 107520

__device__ __nv_bfloat16 g_pb[45875200];   // bs<=16: p0|p1|p2 bf16
__device__ __nv_bfloat16 g_wb[456960];     // w0|w1|w2 bf16

__device__ __forceinline__ uint32_t smem_u32(const void* p) {
    uint32_t a;
    asm("{ .reg .u64 t; cvta.to.shared.u64 t, %1; cvt.u32.u64 %0, t; }"
        : "=r"(a) : "l"(p));
    return a;
}
__device__ __forceinline__ void cp16(uint32_t saddr, const void* gaddr) {
    asm volatile("cp.async.cg.shared.global [%0], [%1], 16;"
                 :: "r"(saddr), "l"(gaddr) : "memory");
}
__device__ __forceinline__ uint32_t pack2(float a, float b) {
    __nv_bfloat162 h = __floats2bfloat162_rn(a, b);
    return *reinterpret_cast<uint32_t*>(&h);
}

// ---------------- K1: fp32 -> bf16 convert ----------------
__global__ void cvt_kernel(const float* __restrict__ p0, const float* __restrict__ p1,
                           const float* __restrict__ p2,
                           const float* __restrict__ w0, const float* __restrict__ w1,
                           const float* __restrict__ w2, int bs)
{
    const size_t N0 = (size_t)bs * 409600;
    const size_t N1 = (size_t)bs * 204800;
    const size_t N2 = (size_t)bs * 102400;
    const size_t NW0 = 16320, NW1 = 32640, NW2 = 65280;
    size_t i = (size_t)blockIdx.x * blockDim.x + threadIdx.x;
    const float* src; __nv_bfloat16* dst; size_t loc;
    if (i < N0)                 { src = p0; dst = g_pb;                 loc = i; }
    else if (i < N0+N1)         { src = p1; dst = g_pb + N0*4;          loc = i-N0; }
    else if (i < N0+N1+N2)      { src = p2; dst = g_pb + (N0+N1)*4;     loc = i-N0-N1; }
    else if (i < N0+N1+N2+NW0)  { src = w0; dst = g_wb;                 loc = i-N0-N1-N2; }
    else if (i < N0+N1+N2+NW0+NW1) { src = w1; dst = g_wb + 65280;      loc = i-N0-N1-N2-NW0; }
    else if (i < N0+N1+N2+NW0+NW1+NW2) { src = w2; dst = g_wb + 195840; loc = i-N0-N1-N2-NW0-NW1; }
    else return;
    float4 v = reinterpret_cast<const float4*>(src)[loc];
    uint2 o;
    o.x = pack2(v.x, v.y);
    o.y = pack2(v.z, v.w);
    reinterpret_cast<uint2*>(dst)[loc] = o;
}

// ---------------- K2: bf16 GEMM + decode ----------------
__global__ __launch_bounds__(256, 2)
void yolo_bf16_kernel(const float* __restrict__ bb0, const float* __restrict__ bb1,
                      const float* __restrict__ bb2,
                      const float* __restrict__ anchors,
                      float* __restrict__ out,
                      int bs, int t2, int t1)
{
    extern __shared__ __align__(16) char dsm[];
    __shared__ float bias_s[256];
    __shared__ float anc_s[8];

    const int tid  = threadIdx.x;
    const int lane = tid & 31;
    const int wid  = tid >> 5;
    const int wm   = wid >> 2;     // 0..1
    const int wn   = wid & 3;      // 0..3
    const int gid  = lane >> 2;    // 0..7
    const int tig  = lane & 3;     // 0..3

    // ---- scale dispatch (scale 2 first: deepest K) ----
    int bid = blockIdx.x;
    const __nv_bfloat16 *p, *wmat;
    const float *bi, *anc;
    int C, S, nx, row_off;
    float strd;
    const size_t o1 = (size_t)bs * 1638400;
    const size_t o2 = o1 + (size_t)bs * 819200;
    if (bid < 2 * t2) {
        p = g_pb + o2; wmat = g_wb + 195840; bi = bb2; anc = anchors + 12;
        C = 1024; S = 400; nx = 20; strd = 32.f; row_off = 24000;
    } else if (bid < 2 * (t2 + t1)) {
        bid -= 2 * t2;
        p = g_pb + o1; wmat = g_wb + 65280; bi = bb1; anc = anchors + 6;
        C = 512; S = 1600; nx = 40; strd = 16.f; row_off = 19200;
    } else {
        bid -= 2 * (t2 + t1);
        p = g_pb; wmat = g_wb; bi = bb0; anc = anchors;
        C = 256; S = 6400; nx = 80; strd = 8.f; row_off = 0;
    }
    const int m0   = (bid >> 1) << 7;
    const int n0   = (bid & 1) << 7;
    const int Mtot = bs * S;

    if (tid < 255) bias_s[tid] = bi[tid];
    if (tid < 6)   anc_s[tid]  = anc[tid];

    const uint32_t smem_base = smem_u32(dsm);

    // ---- producer mappings (hoisted, per-thread constant) ----
    // A: 64 k-rows x 256B per chunk; op(o): k = (tid>>4) + o*16, o=0..3
    const int a_m8 = (tid & 15) * 8;
    const int a_kb = tid >> 4;
    int pm = m0 + a_m8;
    if (pm > Mtot - 8) pm = Mtot - 8;
    const int ab  = pm / S;
    const int as_ = pm - ab * S;
    const __nv_bfloat16* aG = p + ((size_t)ab * (size_t)C) * (size_t)S + (size_t)as_;
    // B: 128 n-rows x 128B per chunk; n fixed per thread, j = (tid&1) + o*2, o=0..3
    const int b_n  = tid >> 1;
    const int b_j0 = tid & 1;
    int bng = n0 + b_n; if (bng > 254) bng = 254;
    const __nv_bfloat16* bG = wmat + (size_t)bng * (size_t)C;
    const uint32_t b_sbase = (uint32_t)(A_ST_BYTES + b_n * B_ROW_B + b_j0 * 16);

    // ---- ldmatrix addresses ----
    const int a_krow = (lane & 7) + ((lane >> 4) & 1) * 8;
    const int a_mcol = lane & 8;
    uint32_t aAddr[4];
    #pragma unroll
    for (int mt = 0; mt < 4; mt++)
        aAddr[mt] = smem_base + (uint32_t)(a_krow * A_ROW_B
                  + (wm * 64 + mt * 16 + a_mcol) * 2);
    const int b_row4 = ((lane >> 4) & 1) * 8 + (lane & 7);
    const int b_koff = ((lane >> 3) & 1) * 16;
    uint32_t bAddr[2];
    #pragma unroll
    for (int pr = 0; pr < 2; pr++)
        bAddr[pr] = smem_base + A_ST_BYTES
                  + (uint32_t)((wn * 32 + pr * 16 + b_row4) * B_ROW_B) + b_koff;

    float acc[4][4][4] = {};
    const int nk = C >> 6;

    auto issue = [&](int stage, int chunk) {
        const uint32_t sb = smem_base + (uint32_t)stage * STAGE_B;
        const int kc0 = chunk << 6;
        #pragma unroll
        for (int o = 0; o < 4; o++) {
            const int k = a_kb + o * 16;
            cp16(sb + (uint32_t)(k * A_ROW_B + a_m8 * 2),
                 aG + (size_t)(kc0 + k) * (size_t)S);
        }
        #pragma unroll
        for (int o = 0; o < 4; o++) {
            const int j = b_j0 + o * 2;              // 16B unit within 128B row
            cp16(sb + b_sbase + (uint32_t)(o * 32),
                 bG + (size_t)(kc0 + j * 8));
        }
        asm volatile("cp.async.commit_group;" ::: "memory");
    };

    // ---- prologue: 2 stages in flight ----
    issue(0, 0);
    if (nk > 1) issue(1, 1); else asm volatile("cp.async.commit_group;" ::: "memory");

    // ---- main loop: K chunks of 64 (4 k16-steps per chunk) ----
    for (int it = 0; it < nk; ++it) {
        asm volatile("cp.async.wait_group 1;" ::: "memory");
        __syncthreads();
        if (it + 2 < nk) issue((it + 2) % NST, it + 2);
        else             asm volatile("cp.async.commit_group;" ::: "memory");

        const uint32_t soff = (uint32_t)(it % NST) * STAGE_B;
        #pragma unroll
        for (int ks = 0; ks < 4; ks++) {
            uint32_t af[4][4], bf[2][4];
            #pragma unroll
            for (int mt = 0; mt < 4; mt++)
                asm volatile("ldmatrix.sync.aligned.m8n8.x4.trans.shared.b16 {%0,%1,%2,%3}, [%4];"
                             : "=r"(af[mt][0]), "=r"(af[mt][1]), "=r"(af[mt][2]), "=r"(af[mt][3])
                             : "r"(aAddr[mt] + soff + ks * (16 * A_ROW_B)));
            #pragma unroll
            for (int pr = 0; pr < 2; pr++)
                asm volatile("ldmatrix.sync.aligned.m8n8.x4.shared.b16 {%0,%1,%2,%3}, [%4];"
                             : "=r"(bf[pr][0]), "=r"(bf[pr][1]), "=r"(bf[pr][2]), "=r"(bf[pr][3])
                             : "r"(bAddr[pr] + soff + ks * 32));
            #pragma unroll
            for (int mt = 0; mt < 4; mt++)
                #pragma unroll
                for (int nt = 0; nt < 4; nt++)
                    asm volatile(
                        "mma.sync.aligned.m16n8k16.row.col.f32.bf16.bf16.f32 "
                        "{%0,%1,%2,%3}, {%4,%5,%6,%7}, {%8,%9}, {%0,%1,%2,%3};"
                        : "+f"(acc[mt][nt][0]), "+f"(acc[mt][nt][1]),
                          "+f"(acc[mt][nt][2]), "+f"(acc[mt][nt][3])
                        : "r"(af[mt][0]), "r"(af[mt][1]), "r"(af[mt][2]), "r"(af[mt][3]),
                          "r"(bf[nt >> 1][(nt & 1) * 2]), "r"(bf[nt >> 1][(nt & 1) * 2 + 1]));
        }
    }

    // ---- epilogue: bias + sigmoid + decode + scattered store ----
    const float aw[3] = { anc_s[0], anc_s[2], anc_s[4] };
    const float ah[3] = { anc_s[1], anc_s[3], anc_s[5] };
    const size_t sS85 = (size_t)S * 85u;
    const int total_rows = 25200;

    #pragma unroll
    for (int mt = 0; mt < 4; mt++) {
        #pragma unroll
        for (int half = 0; half < 2; half++) {
            const int m = m0 + wm * 64 + mt * 16 + gid + half * 8;
            if (m >= Mtot) continue;
            const int b  = m / S;
            const int s  = m - b * S;
            const int yy = s / nx;
            const int xx = s - yy * nx;
            const float fxx = (float)xx - 0.5f;
            const float fyy = (float)yy - 0.5f;
            const size_t base = ((size_t)b * (size_t)total_rows + (size_t)row_off + (size_t)s) * 85u;
            #pragma unroll
            for (int nt = 0; nt < 4; nt++) {
                const int n = n0 + wn * 32 + nt * 8 + 2 * tig;
                #pragma unroll
                for (int e = 0; e < 2; e++) {
                    const int nn = n + e;
                    if (nn >= 255) continue;
                    float v  = acc[mt][nt][half * 2 + e] + bias_s[nn];
                    float sg = 1.f / (1.f + __expf(-v));
                    int a = (nn >= 170) ? 2 : ((nn >= 85) ? 1 : 0);
                    int c = nn - a * 85;
                    float o;
                    if (c == 0)      o = (2.f * sg + fxx) * strd;
                    else if (c == 1) o = (2.f * sg + fyy) * strd;
                    else if (c == 2) { float t = 2.f * sg; o = t * t * aw[a]; }
                    else if (c == 3) { float t = 2.f * sg; o = t * t * ah[a]; }
                    else             o = sg;
                    out[base + (size_t)a * sS85 + (size_t)c] = o;
                }
            }
        }
    }
}

extern "C" void kernel_launch(void* const* d_in, const int* in_sizes, int n_in,
                              void* d_out, int out_size)
{
    const float* p0 = (const float*)d_in[0];
    const float* p1 = (const float*)d_in[1];
    const float* p2 = (const float*)d_in[2];
    const float* w0 = (const float*)d_in[3];
    const float* b0 = (const float*)d_in[4];
    const float* w1 = (const float*)d_in[5];
    const float* b1 = (const float*)d_in[6];
    const float* w2 = (const float*)d_in[7];
    const float* b2 = (const float*)d_in[8];
    const float* anchors = (const float*)d_in[9];
    float* out = (float*)d_out;

    cudaFuncSetAttribute(yolo_bf16_kernel,
                         cudaFuncAttributeMaxDynamicSharedMemorySize, DSMEM);

    const int bs = in_sizes[0] / (256 * 80 * 80);

    // K1: convert
    {
        size_t total4 = (size_t)bs * (409600 + 204800 + 102400) + 16320 + 32640 + 65280;
        int grid = (int)((total4 + 255) / 256);
        cvt_kernel<<<grid, 256>>>(p0, p1, p2, w0, w1, w2, bs);
    }

    // K2: GEMM + decode
    {
        const int t2 = (bs * 400  + 127) / 128;
        const int t1 = (bs * 1600 + 127) / 128;
        const int t0 = (bs * 6400 + 127) / 128;
        const int grid = 2 * (t0 + t1 + t2);
        yolo_bf16_kernel<<<grid, 256, DSMEM>>>(b0, b1, b2, anchors, out, bs, t2, t1);
    }
}

// round 17
// speedup vs baseline: 1.1660x; 1.1660x over previous
#include <cuda_runtime.h>
#include <cuda_bf16.h>
#include <cstdint>

// YOLOv5 detect head, two-kernel scheme:
//  K1: stream-convert p0/p1/p2/w* fp32 -> bf16 into __device__ scratch.
//  K2: unified bf16 GEMM (mma.m16n8k16). CTA 128m x 64n (warp tile 32x32,
//      3 CTAs/SM for occupancy), K chunks of 32, 4-stage cp.async ring,
//      ldmatrix fragments (A: x4.trans, 272B rows; B: x4, 80B rows; both
//      conflict-free), scattered decode epilogue.

#define A_ROW_B 272                    // 128 bf16 (256B) + 16B pad (17 units)
#define A_ST_BYTES (32 * A_ROW_B)      // 8704
#define B_ROW_B 80                     // 32 bf16 (64B) + 16B pad (5 units)
#define B_ST_BYTES (64 * B_ROW_B)      // 5120
#define STAGE_B (A_ST_BYTES + B_ST_BYTES)  // 13824
#define NST 4
#define DSMEM (NST * STAGE_B)          // 55296

__device__ __nv_bfloat16 g_pb[45875200];   // bs<=16: p0|p1|p2 bf16
__device__ __nv_bfloat16 g_wb[456960];     // w0|w1|w2 bf16

__device__ __forceinline__ uint32_t smem_u32(const void* p) {
    uint32_t a;
    asm("{ .reg .u64 t; cvta.to.shared.u64 t, %1; cvt.u32.u64 %0, t; }"
        : "=r"(a) : "l"(p));
    return a;
}
__device__ __forceinline__ void cp16(uint32_t saddr, const void* gaddr) {
    asm volatile("cp.async.cg.shared.global [%0], [%1], 16;"
                 :: "r"(saddr), "l"(gaddr) : "memory");
}
__device__ __forceinline__ uint32_t pack2(float a, float b) {
    __nv_bfloat162 h = __floats2bfloat162_rn(a, b);
    return *reinterpret_cast<uint32_t*>(&h);
}

// ---------------- K1: fp32 -> bf16 convert ----------------
__global__ void cvt_kernel(const float* __restrict__ p0, const float* __restrict__ p1,
                           const float* __restrict__ p2,
                           const float* __restrict__ w0, const float* __restrict__ w1,
                           const float* __restrict__ w2, int bs)
{
    const size_t N0 = (size_t)bs * 409600;
    const size_t N1 = (size_t)bs * 204800;
    const size_t N2 = (size_t)bs * 102400;
    const size_t NW0 = 16320, NW1 = 32640, NW2 = 65280;
    size_t i = (size_t)blockIdx.x * blockDim.x + threadIdx.x;
    const float* src; __nv_bfloat16* dst; size_t loc;
    if (i < N0)                 { src = p0; dst = g_pb;                 loc = i; }
    else if (i < N0+N1)         { src = p1; dst = g_pb + N0*4;          loc = i-N0; }
    else if (i < N0+N1+N2)      { src = p2; dst = g_pb + (N0+N1)*4;     loc = i-N0-N1; }
    else if (i < N0+N1+N2+NW0)  { src = w0; dst = g_wb;                 loc = i-N0-N1-N2; }
    else if (i < N0+N1+N2+NW0+NW1) { src = w1; dst = g_wb + 65280;      loc = i-N0-N1-N2-NW0; }
    else if (i < N0+N1+N2+NW0+NW1+NW2) { src = w2; dst = g_wb + 195840; loc = i-N0-N1-N2-NW0-NW1; }
    else return;
    float4 v = reinterpret_cast<const float4*>(src)[loc];
    uint2 o;
    o.x = pack2(v.x, v.y);
    o.y = pack2(v.z, v.w);
    reinterpret_cast<uint2*>(dst)[loc] = o;
}

// ---------------- K2: bf16 GEMM + decode ----------------
__global__ __launch_bounds__(256, 3)
void yolo_bf16_kernel(const float* __restrict__ bb0, const float* __restrict__ bb1,
                      const float* __restrict__ bb2,
                      const float* __restrict__ anchors,
                      float* __restrict__ out,
                      int bs, int t2, int t1)
{
    extern __shared__ __align__(16) char dsm[];
    __shared__ float bias_s[256];
    __shared__ float anc_s[8];

    const int tid  = threadIdx.x;
    const int lane = tid & 31;
    const int wid  = tid >> 5;
    const int wm   = wid >> 1;     // 0..3  (32 m-rows each)
    const int wn   = wid & 1;      // 0..1  (32 n-cols each)
    const int gid  = lane >> 2;    // 0..7
    const int tig  = lane & 3;     // 0..3

    // ---- scale dispatch (scale 2 first: deepest K) ----
    int bid = blockIdx.x;
    const __nv_bfloat16 *p, *wmat;
    const float *bi, *anc;
    int C, S, nx, row_off;
    float strd;
    const size_t o1 = (size_t)bs * 1638400;
    const size_t o2 = o1 + (size_t)bs * 819200;
    if (bid < 4 * t2) {
        p = g_pb + o2; wmat = g_wb + 195840; bi = bb2; anc = anchors + 12;
        C = 1024; S = 400; nx = 20; strd = 32.f; row_off = 24000;
    } else if (bid < 4 * (t2 + t1)) {
        bid -= 4 * t2;
        p = g_pb + o1; wmat = g_wb + 65280; bi = bb1; anc = anchors + 6;
        C = 512; S = 1600; nx = 40; strd = 16.f; row_off = 19200;
    } else {
        bid -= 4 * (t2 + t1);
        p = g_pb; wmat = g_wb; bi = bb0; anc = anchors;
        C = 256; S = 6400; nx = 80; strd = 8.f; row_off = 0;
    }
    const int m0   = (bid >> 2) << 7;
    const int n0   = (bid & 3) << 6;
    const int Mtot = bs * S;

    if (tid < 255) bias_s[tid] = bi[tid];
    if (tid < 6)   anc_s[tid]  = anc[tid];

    const uint32_t smem_base = smem_u32(dsm);

    // ---- producer mappings ----
    // A: 32 k-rows x 256B; op(o): k = (tid>>4) + o*16, m8 = (tid&15)*8
    const int a_m8 = (tid & 15) * 8;
    const int a_kb = tid >> 4;
    int pm = m0 + a_m8;
    if (pm > Mtot - 8) pm = Mtot - 8;
    const int ab  = pm / S;
    const int as_ = pm - ab * S;
    const __nv_bfloat16* aG = p + ((size_t)ab * (size_t)C) * (size_t)S + (size_t)as_;
    // B: 64 n-rows x 64B; 1 op: n = tid>>2, j = tid&3
    const int b_n = tid >> 2;
    const int b_j = tid & 3;
    int bng = n0 + b_n; if (bng > 254) bng = 254;
    const __nv_bfloat16* bG = wmat + (size_t)bng * (size_t)C + (size_t)(b_j * 8);
    const uint32_t b_sbase = (uint32_t)(A_ST_BYTES + b_n * B_ROW_B + b_j * 16);

    // ---- ldmatrix addresses ----
    const int a_krow = (lane & 7) + ((lane >> 4) & 1) * 8;
    const int a_mcol = lane & 8;
    uint32_t aAddr[2];
    #pragma unroll
    for (int mt = 0; mt < 2; mt++)
        aAddr[mt] = smem_base + (uint32_t)(a_krow * A_ROW_B
                  + (wm * 32 + mt * 16 + a_mcol) * 2);
    const int b_row4 = ((lane >> 4) & 1) * 8 + (lane & 7);
    const int b_koff = ((lane >> 3) & 1) * 16;
    uint32_t bAddr[2];
    #pragma unroll
    for (int pr = 0; pr < 2; pr++)
        bAddr[pr] = smem_base + A_ST_BYTES
                  + (uint32_t)((wn * 32 + pr * 16 + b_row4) * B_ROW_B) + b_koff;

    float acc[2][4][4] = {};
    const int nk = C >> 5;

    auto issue = [&](int stage, int chunk) {
        const uint32_t sb = smem_base + (uint32_t)stage * STAGE_B;
        const int kc0 = chunk << 5;
        #pragma unroll
        for (int o = 0; o < 2; o++) {
            const int k = a_kb + o * 16;
            cp16(sb + (uint32_t)(k * A_ROW_B + a_m8 * 2),
                 aG + (size_t)(kc0 + k) * (size_t)S);
        }
        cp16(sb + b_sbase, bG + (size_t)kc0);
        asm volatile("cp.async.commit_group;" ::: "memory");
    };

    // ---- prologue: 3 stages in flight ----
    issue(0, 0);
    issue(1, 1);
    issue(2, 2);

    // ---- main loop ----
    for (int it = 0; it < nk; ++it) {
        asm volatile("cp.async.wait_group 2;" ::: "memory");
        __syncthreads();
        if (it + 3 < nk) issue((it + 3) & 3, it + 3);
        else             asm volatile("cp.async.commit_group;" ::: "memory");

        const uint32_t soff = (uint32_t)(it & 3) * STAGE_B;
        #pragma unroll
        for (int ks = 0; ks < 2; ks++) {
            uint32_t af[2][4], bf[2][4];
            #pragma unroll
            for (int mt = 0; mt < 2; mt++)
                asm volatile("ldmatrix.sync.aligned.m8n8.x4.trans.shared.b16 {%0,%1,%2,%3}, [%4];"
                             : "=r"(af[mt][0]), "=r"(af[mt][1]), "=r"(af[mt][2]), "=r"(af[mt][3])
                             : "r"(aAddr[mt] + soff + ks * (16 * A_ROW_B)));
            #pragma unroll
            for (int pr = 0; pr < 2; pr++)
                asm volatile("ldmatrix.sync.aligned.m8n8.x4.shared.b16 {%0,%1,%2,%3}, [%4];"
                             : "=r"(bf[pr][0]), "=r"(bf[pr][1]), "=r"(bf[pr][2]), "=r"(bf[pr][3])
                             : "r"(bAddr[pr] + soff + ks * 32));
            #pragma unroll
            for (int mt = 0; mt < 2; mt++)
                #pragma unroll
                for (int nt = 0; nt < 4; nt++)
                    asm volatile(
                        "mma.sync.aligned.m16n8k16.row.col.f32.bf16.bf16.f32 "
                        "{%0,%1,%2,%3}, {%4,%5,%6,%7}, {%8,%9}, {%0,%1,%2,%3};"
                        : "+f"(acc[mt][nt][0]), "+f"(acc[mt][nt][1]),
                          "+f"(acc[mt][nt][2]), "+f"(acc[mt][nt][3])
                        : "r"(af[mt][0]), "r"(af[mt][1]), "r"(af[mt][2]), "r"(af[mt][3]),
                          "r"(bf[nt >> 1][(nt & 1) * 2]), "r"(bf[nt >> 1][(nt & 1) * 2 + 1]));
        }
    }

    // ---- epilogue: bias + sigmoid + decode + scattered store ----
    const float aw[3] = { anc_s[0], anc_s[2], anc_s[4] };
    const float ah[3] = { anc_s[1], anc_s[3], anc_s[5] };
    const size_t sS85 = (size_t)S * 85u;
    const int total_rows = 25200;

    #pragma unroll
    for (int mt = 0; mt < 2; mt++) {
        #pragma unroll
        for (int half = 0; half < 2; half++) {
            const int m = m0 + wm * 32 + mt * 16 + gid + half * 8;
            if (m >= Mtot) continue;
            const int b  = m / S;
            const int s  = m - b * S;
            const int yy = s / nx;
            const int xx = s - yy * nx;
            const float fxx = (float)xx - 0.5f;
            const float fyy = (float)yy - 0.5f;
            const size_t base = ((size_t)b * (size_t)total_rows + (size_t)row_off + (size_t)s) * 85u;
            #pragma unroll
            for (int nt = 0; nt < 4; nt++) {
                const int n = n0 + wn * 32 + nt * 8 + 2 * tig;
                #pragma unroll
                for (int e = 0; e < 2; e++) {
                    const int nn = n + e;
                    if (nn >= 255) continue;
                    float v  = acc[mt][nt][half * 2 + e] + bias_s[nn];
                    float sg = 1.f / (1.f + __expf(-v));
                    int a = (nn >= 170) ? 2 : ((nn >= 85) ? 1 : 0);
                    int c = nn - a * 85;
                    float o;
                    if (c == 0)      o = (2.f * sg + fxx) * strd;
                    else if (c == 1) o = (2.f * sg + fyy) * strd;
                    else if (c == 2) { float t = 2.f * sg; o = t * t * aw[a]; }
                    else if (c == 3) { float t = 2.f * sg; o = t * t * ah[a]; }
                    else             o = sg;
                    out[base + (size_t)a * sS85 + (size_t)c] = o;
                }
            }
        }
    }
}

extern "C" void kernel_launch(void* const* d_in, const int* in_sizes, int n_in,
                              void* d_out, int out_size)
{
    const float* p0 = (const float*)d_in[0];
    const float* p1 = (const float*)d_in[1];
    const float* p2 = (const float*)d_in[2];
    const float* w0 = (const float*)d_in[3];
    const float* b0 = (const float*)d_in[4];
    const float* w1 = (const float*)d_in[5];
    const float* b1 = (const float*)d_in[6];
    const float* w2 = (const float*)d_in[7];
    const float* b2 = (const float*)d_in[8];
    const float* anchors = (const float*)d_in[9];
    float* out = (float*)d_out;

    cudaFuncSetAttribute(yolo_bf16_kernel,
                         cudaFuncAttributeMaxDynamicSharedMemorySize, DSMEM);

    const int bs = in_sizes[0] / (256 * 80 * 80);

    // K1: convert
    {
        size_t total4 = (size_t)bs * (409600 + 204800 + 102400) + 16320 + 32640 + 65280;
        int grid = (int)((total4 + 255) / 256);
        cvt_kernel<<<grid, 256>>>(p0, p1, p2, w0, w1, w2, bs);
    }

    // K2: GEMM + decode
    {
        const int t2 = (bs * 400  + 127) / 128;
        const int t1 = (bs * 1600 + 127) / 128;
        const int t0 = (bs * 6400 + 127) / 128;
        const int grid = 4 * (t0 + t1 + t2);
        yolo_bf16_kernel<<<grid, 256, DSMEM>>>(b0, b1, b2, anchors, out, bs, t2, t1);
    }
}